// round 15
// baseline (speedup 1.0000x reference)
#include <cuda_runtime.h>
#include <cuda_bf16.h>
#include <cstdint>
#include <math.h>

// Problem constants
#define NSEQ   2048
#define DIM    2048
#define NHEAD  32
#define KVH    4
#define REP    8
#define HD     64
#define KV_DIM 256
#define SCALE  0.125f

// Scratch
__device__ float g_Q[NSEQ * DIM];
__device__ float g_K[NSEQ * KV_DIM];
__device__ float g_V[NSEQ * KV_DIM];
__device__ float g_Y[NSEQ * DIM];

// Round fp32 -> tf32 (round-to-nearest) kept in a float container.
__device__ __forceinline__ float tf32r(float x) {
    unsigned int r;
    asm("cvt.rna.tf32.f32 %0, %1;" : "=r"(r) : "f"(x));
    return __uint_as_float(r);
}

// m16n8k8 tf32 mma, acc fp32
__device__ __forceinline__ void mma_tf32(float c[4], const float a[4], const float b[2]) {
    asm volatile(
        "mma.sync.aligned.m16n8k8.row.col.f32.tf32.tf32.f32 "
        "{%0,%1,%2,%3}, {%4,%5,%6,%7}, {%8,%9}, {%0,%1,%2,%3};\n"
        : "+f"(c[0]), "+f"(c[1]), "+f"(c[2]), "+f"(c[3])
        : "r"(__float_as_uint(a[0])), "r"(__float_as_uint(a[1])),
          "r"(__float_as_uint(a[2])), "r"(__float_as_uint(a[3])),
          "r"(__float_as_uint(b[0])), "r"(__float_as_uint(b[1])));
}

// 16-byte async copy gmem -> smem (L2-only path)
__device__ __forceinline__ void cp16(float* s, const float* g) {
    unsigned int sa = (unsigned int)__cvta_generic_to_shared(s);
    asm volatile("cp.async.cg.shared.global [%0], [%1], 16;" :: "r"(sa), "l"(g));
}
#define CP_COMMIT()  asm volatile("cp.async.commit_group;")

// ---------------------------------------------------------------------------
// GEMM: C[M,Nc] = A[M,K] * B[Nc,K]^T via tf32 mma.sync.
// Block 128x128, BK=32, 8 warps (2x4), warp tile 64x32.
// 3-stage cp.async smem pipeline; one __syncthreads per K-tile.
// tf32 rounding applied at fragment load (bit-identical to store-side cvt).
// ---------------------------------------------------------------------------
#define BK 32
#define APAD 36       // 36 % 32 == 4 -> conflict-free fragment loads
#define NSTG 3
#define TILE_F (128 * APAD)

__global__ __launch_bounds__(256) void gemm_tf32(
    const float* __restrict__ A,
    const float* __restrict__ B0, const float* __restrict__ B1,
    float* __restrict__ C0, float* __restrict__ C1,
    int M, int Nc, int K)
{
    extern __shared__ float sh[];   // [NSTG][2][TILE_F]

    const float* __restrict__ B = blockIdx.z ? B1 : B0;
    float* __restrict__ C = blockIdx.z ? C1 : C0;

    const int tid  = threadIdx.x;
    const int warp = tid >> 5, lane = tid & 31;
    const int g = lane >> 2, tig = lane & 3;
    const int wm = warp >> 2;
    const int wn = warp & 3;
    const int row0 = blockIdx.y * 128;
    const int col0 = blockIdx.x * 128;

    float acc[4][4][4];
    #pragma unroll
    for (int mt = 0; mt < 4; ++mt)
        #pragma unroll
        for (int nt = 0; nt < 4; ++nt)
            #pragma unroll
            for (int r = 0; r < 4; ++r) acc[mt][nt][r] = 0.f;

    const int T = K / BK;

    auto issue = [&](int t) {
        float* as = sh + (t % NSTG) * 2 * TILE_F;
        float* bs = as + TILE_F;
        #pragma unroll
        for (int i = 0; i < 4; ++i) {
            int f = tid + i * 256;
            int r = f >> 3, c = (f & 7) * 4;
            cp16(&as[r * APAD + c], A + (size_t)(row0 + r) * K + t * BK + c);
            cp16(&bs[r * APAD + c], B + (size_t)(col0 + r) * K + t * BK + c);
        }
        CP_COMMIT();
    };

    issue(0);
    issue(1);

    for (int t = 0; t < T; ++t) {
        if (t + 1 < T) asm volatile("cp.async.wait_group 1;" ::: "memory");
        else           asm volatile("cp.async.wait_group 0;" ::: "memory");
        __syncthreads();
        if (t + 2 < T) issue(t + 2);

        const float* as = sh + (t % NSTG) * 2 * TILE_F;
        const float* bs = as + TILE_F;

        #pragma unroll
        for (int ks = 0; ks < 4; ++ks) {
            float a[4][4];
            #pragma unroll
            for (int mt = 0; mt < 4; ++mt) {
                int rb_ = wm * 64 + mt * 16;
                a[mt][0] = tf32r(as[(rb_ + g)     * APAD + ks * 8 + tig]);
                a[mt][1] = tf32r(as[(rb_ + g + 8) * APAD + ks * 8 + tig]);
                a[mt][2] = tf32r(as[(rb_ + g)     * APAD + ks * 8 + tig + 4]);
                a[mt][3] = tf32r(as[(rb_ + g + 8) * APAD + ks * 8 + tig + 4]);
            }
            float b[4][2];
            #pragma unroll
            for (int nt = 0; nt < 4; ++nt) {
                int cb = wn * 32 + nt * 8 + g;
                b[nt][0] = tf32r(bs[cb * APAD + ks * 8 + tig]);
                b[nt][1] = tf32r(bs[cb * APAD + ks * 8 + tig + 4]);
            }
            #pragma unroll
            for (int mt = 0; mt < 4; ++mt)
                #pragma unroll
                for (int nt = 0; nt < 4; ++nt)
                    mma_tf32(acc[mt][nt], a[mt], b[nt]);
        }
    }

    #pragma unroll
    for (int mt = 0; mt < 4; ++mt) {
        int r = row0 + wm * 64 + mt * 16 + g;
        #pragma unroll
        for (int nt = 0; nt < 4; ++nt) {
            int c = col0 + wn * 32 + nt * 8 + 2 * tig;
            *(float2*)(C + (size_t)r * Nc + c) =
                make_float2(acc[mt][nt][0], acc[mt][nt][1]);
            *(float2*)(C + (size_t)(r + 8) * Nc + c) =
                make_float2(acc[mt][nt][2], acc[mt][nt][3]);
        }
    }
}

// ---------------------------------------------------------------------------
// RoPE in-place on Q [N,H,64] and K [N,KVH,64]
// ---------------------------------------------------------------------------
__global__ __launch_bounds__(256) void rope_kernel(
    const float* __restrict__ cosT, const float* __restrict__ sinT)
{
    const int QP = NSEQ * NHEAD * 32;
    const int KP = NSEQ * KVH * 32;
    int idx = blockIdx.x * blockDim.x + threadIdx.x;
    if (idx >= QP + KP) return;

    float* base;
    int n, d;
    if (idx < QP) {
        n = idx / (NHEAD * 32);
        int rem = idx % (NHEAD * 32);
        int h = rem >> 5;
        d = rem & 31;
        base = g_Q + (size_t)n * DIM + h * HD;
    } else {
        int k = idx - QP;
        n = k / (KVH * 32);
        int rem = k % (KVH * 32);
        int h = rem >> 5;
        d = rem & 31;
        base = g_K + (size_t)n * KV_DIM + h * HD;
    }
    float c = cosT[n * HD + d];
    float s = sinT[n * HD + d];
    float x0 = base[d];
    float x1 = base[d + 32];
    base[d]      = x0 * c - x1 * s;
    base[d + 32] = x1 * c + x0 * s;
}

// ---------------------------------------------------------------------------
// Flash attention (causal, GQA), tf32 mma.
// Block = 4 warps, 128 q-rows (warp owns 32 rows as two m16 fragments).
// KV tile = 64. P via shfl repack (no smem round-trip).
// Interleaved column layout: logical k stored at (k&~7)|((k&3)<<1)|((k>>2)&1)
// so fragment pairs (k, k+4) are adjacent -> conflict-free LDS.64.
// __launch_bounds__(128, 3): cap regs for 3 blocks/SM (12 warps).
// ---------------------------------------------------------------------------
#define AP 68       // 68 % 32 == 4 -> conflict-free fragment loads
#define QROWS 128

__device__ __forceinline__ int ilv(int k) {   // interleave permutation
    return (k & ~7) | ((k & 3) << 1) | ((k >> 2) & 1);
}

__global__ __launch_bounds__(128, 3) void attn_mma(float* __restrict__ Y)
{
    extern __shared__ float sm[];
    float* Qs = sm;                    // 128*AP
    float* Ks = Qs + QROWS * AP;       // 64*AP
    float* Vt = Ks + 64 * AP;          // 64*AP (Vt[d][ilv(s)])

    const int h  = blockIdx.x;
    const int q0 = (gridDim.y - 1 - blockIdx.y) * QROWS;  // heavy tiles first
    const int kh = h >> 3;

    const int tid  = threadIdx.x;
    const int warp = tid >> 5, lane = tid & 31;
    const int g = lane >> 2, tig = lane & 3;
    const bool odd = tig & 1;
    const int src_lo = (lane & ~3) | (tig >> 1);   // repack shuffle sources
    const int src_hi = src_lo + 2;

    // Load Q tile (128 rows), fold softmax scale, interleaved columns
    #pragma unroll
    for (int f = tid; f < QROWS * 16; f += 128) {
        int r = f >> 4, c4 = (f & 15) * 4;
        int pc = (c4 & ~7) + ((c4 >> 2) & 1);   // ilv of c4; +2 per element
        float4 v = *(const float4*)(g_Q + (size_t)(q0 + r) * DIM + h * HD + c4);
        Qs[r * AP + pc + 0] = tf32r(v.x * SCALE);
        Qs[r * AP + pc + 2] = tf32r(v.y * SCALE);
        Qs[r * AP + pc + 4] = tf32r(v.z * SCALE);
        Qs[r * AP + pc + 6] = tf32r(v.w * SCALE);
    }

    float O[2][8][4];
    #pragma unroll
    for (int mt = 0; mt < 2; ++mt)
        #pragma unroll
        for (int nt = 0; nt < 8; ++nt)
            #pragma unroll
            for (int r = 0; r < 4; ++r) O[mt][nt][r] = 0.f;
    float m[2][2] = {{-1e30f, -1e30f}, {-1e30f, -1e30f}};
    float l[2][2] = {{0.f, 0.f}, {0.f, 0.f}};

    const int ntiles = q0 / 64 + 2;   // covers kv in [0, q0+128)
    for (int t = 0; t < ntiles; ++t) {
        const int k0 = t * 64;
        __syncthreads();   // previous tile's reads done (also Q stores at t=0)
        #pragma unroll
        for (int f = tid; f < 64 * 16; f += 128) {
            int r = f >> 4, c4 = (f & 15) * 4;
            int pc = (c4 & ~7) + ((c4 >> 2) & 1);
            int pr = ilv(r);
            float4 kv = *(const float4*)(g_K + (size_t)(k0 + r) * KV_DIM + kh * HD + c4);
            float4 vv = *(const float4*)(g_V + (size_t)(k0 + r) * KV_DIM + kh * HD + c4);
            Ks[r * AP + pc + 0] = tf32r(kv.x);
            Ks[r * AP + pc + 2] = tf32r(kv.y);
            Ks[r * AP + pc + 4] = tf32r(kv.z);
            Ks[r * AP + pc + 6] = tf32r(kv.w);
            Vt[(c4 + 0) * AP + pr] = tf32r(vv.x);
            Vt[(c4 + 1) * AP + pr] = tf32r(vv.y);
            Vt[(c4 + 2) * AP + pr] = tf32r(vv.z);
            Vt[(c4 + 3) * AP + pr] = tf32r(vv.w);
        }
        __syncthreads();

        #pragma unroll
        for (int mt = 0; mt < 2; ++mt) {
            const int rbase = 32 * warp + 16 * mt;  // local q-row base of frag
            const int rl = rbase + g;

            // ---- S = Q K^T (16x64) ----
            float S[8][4];
            #pragma unroll
            for (int nt = 0; nt < 8; ++nt)
                #pragma unroll
                for (int r = 0; r < 4; ++r) S[nt][r] = 0.f;

            #pragma unroll
            for (int ks = 0; ks < 8; ++ks) {
                float2 alo = *(const float2*)&Qs[(rbase + g)     * AP + ks * 8 + 2 * tig];
                float2 ahi = *(const float2*)&Qs[(rbase + g + 8) * AP + ks * 8 + 2 * tig];
                float a[4] = {alo.x, ahi.x, alo.y, ahi.y};
                #pragma unroll
                for (int nt = 0; nt < 8; ++nt) {
                    float2 bv = *(const float2*)&Ks[(nt * 8 + g) * AP + ks * 8 + 2 * tig];
                    float b[2] = {bv.x, bv.y};
                    mma_tf32(S[nt], a, b);
                }
            }

            // ---- causal mask (only tiles crossing the diagonal) ----
            if (k0 + 63 > q0 + rbase) {
                const int row0_ = q0 + rl, row1_ = row0_ + 8;
                #pragma unroll
                for (int nt = 0; nt < 8; ++nt) {
                    int cc = k0 + nt * 8 + 2 * tig;
                    if (cc     > row0_) S[nt][0] = -1e30f;
                    if (cc + 1 > row0_) S[nt][1] = -1e30f;
                    if (cc     > row1_) S[nt][2] = -1e30f;
                    if (cc + 1 > row1_) S[nt][3] = -1e30f;
                }
            }

            // ---- online softmax (rows rl and rl+8) ----
            float mx0 = -1e30f, mx1 = -1e30f;
            #pragma unroll
            for (int nt = 0; nt < 8; ++nt) {
                mx0 = fmaxf(mx0, fmaxf(S[nt][0], S[nt][1]));
                mx1 = fmaxf(mx1, fmaxf(S[nt][2], S[nt][3]));
            }
            mx0 = fmaxf(mx0, __shfl_xor_sync(0xffffffff, mx0, 1));
            mx0 = fmaxf(mx0, __shfl_xor_sync(0xffffffff, mx0, 2));
            mx1 = fmaxf(mx1, __shfl_xor_sync(0xffffffff, mx1, 1));
            mx1 = fmaxf(mx1, __shfl_xor_sync(0xffffffff, mx1, 2));

            float mn0 = fmaxf(m[mt][0], mx0), mn1 = fmaxf(m[mt][1], mx1);
            float al0 = __expf(m[mt][0] - mn0), al1 = __expf(m[mt][1] - mn1);

            float s0 = 0.f, s1 = 0.f;
            #pragma unroll
            for (int nt = 0; nt < 8; ++nt) {
                S[nt][0] = tf32r(__expf(S[nt][0] - mn0));
                S[nt][1] = tf32r(__expf(S[nt][1] - mn0));
                S[nt][2] = tf32r(__expf(S[nt][2] - mn1));
                S[nt][3] = tf32r(__expf(S[nt][3] - mn1));
                s0 += S[nt][0] + S[nt][1];
                s1 += S[nt][2] + S[nt][3];
            }
            s0 += __shfl_xor_sync(0xffffffff, s0, 1);
            s0 += __shfl_xor_sync(0xffffffff, s0, 2);
            s1 += __shfl_xor_sync(0xffffffff, s1, 1);
            s1 += __shfl_xor_sync(0xffffffff, s1, 2);

            m[mt][0] = mn0; m[mt][1] = mn1;
            l[mt][0] = l[mt][0] * al0 + s0;
            l[mt][1] = l[mt][1] * al1 + s1;

            #pragma unroll
            for (int nt = 0; nt < 8; ++nt) {
                O[mt][nt][0] *= al0; O[mt][nt][1] *= al0;
                O[mt][nt][2] *= al1; O[mt][nt][3] *= al1;
            }

            // ---- O += P V : repack C-frag -> A-frag via shfl, no smem ----
            #pragma unroll
            for (int ks = 0; ks < 8; ++ks) {
                float x0 = __shfl_sync(0xffffffff, S[ks][0], src_lo);
                float x1 = __shfl_sync(0xffffffff, S[ks][1], src_lo);
                float y0 = __shfl_sync(0xffffffff, S[ks][2], src_lo);
                float y1 = __shfl_sync(0xffffffff, S[ks][3], src_lo);
                float z0 = __shfl_sync(0xffffffff, S[ks][0], src_hi);
                float z1 = __shfl_sync(0xffffffff, S[ks][1], src_hi);
                float w0 = __shfl_sync(0xffffffff, S[ks][2], src_hi);
                float w1 = __shfl_sync(0xffffffff, S[ks][3], src_hi);
                float pa[4];
                pa[0] = odd ? x1 : x0;   // P(row g,   col ks*8+tig)
                pa[1] = odd ? y1 : y0;   // P(row g+8, col ks*8+tig)
                pa[2] = odd ? z1 : z0;   // P(row g,   col ks*8+tig+4)
                pa[3] = odd ? w1 : w0;   // P(row g+8, col ks*8+tig+4)
                #pragma unroll
                for (int nt = 0; nt < 8; ++nt) {
                    float2 bv = *(const float2*)&Vt[(nt * 8 + g) * AP + ks * 8 + 2 * tig];
                    float b[2] = {bv.x, bv.y};
                    mma_tf32(O[mt][nt], pa, b);
                }
            }
        }
    }

    // Normalize + store
    #pragma unroll
    for (int mt = 0; mt < 2; ++mt) {
        const int r = q0 + 32 * warp + 16 * mt + g;
        float inv0 = 1.f / l[mt][0], inv1 = 1.f / l[mt][1];
        #pragma unroll
        for (int nt = 0; nt < 8; ++nt) {
            int c = h * HD + nt * 8 + 2 * tig;
            *(float2*)(Y + (size_t)r * DIM + c) =
                make_float2(O[mt][nt][0] * inv0, O[mt][nt][1] * inv0);
            *(float2*)(Y + (size_t)(r + 8) * DIM + c) =
                make_float2(O[mt][nt][2] * inv1, O[mt][nt][3] * inv1);
        }
    }
}

// ---------------------------------------------------------------------------
// Launch
// ---------------------------------------------------------------------------
extern "C" void kernel_launch(void* const* d_in, const int* in_sizes, int n_in,
                              void* d_out, int out_size)
{
    const float* x    = (const float*)d_in[0];
    const float* Wq   = (const float*)d_in[1];
    const float* Wk   = (const float*)d_in[2];
    const float* Wv   = (const float*)d_in[3];
    const float* Wo   = (const float*)d_in[4];
    const float* cosT = (const float*)d_in[5];
    const float* sinT = (const float*)d_in[6];
    float* out = (float*)d_out;

    float *dQ, *dK, *dV, *dY;
    cudaGetSymbolAddress((void**)&dQ, g_Q);
    cudaGetSymbolAddress((void**)&dK, g_K);
    cudaGetSymbolAddress((void**)&dV, g_V);
    cudaGetSymbolAddress((void**)&dY, g_Y);

    const int gemm_smem = NSTG * 2 * TILE_F * sizeof(float);  // 108 KB
    cudaFuncSetAttribute(gemm_tf32,
                         cudaFuncAttributeMaxDynamicSharedMemorySize, gemm_smem);

    // Q projection
    gemm_tf32<<<dim3(DIM / 128, NSEQ / 128, 1), 256, gemm_smem>>>(
        x, Wq, Wq, dQ, dQ, NSEQ, DIM, DIM);
    // K and V projections fused in one launch
    gemm_tf32<<<dim3(KV_DIM / 128, NSEQ / 128, 2), 256, gemm_smem>>>(
        x, Wk, Wv, dK, dV, NSEQ, KV_DIM, DIM);

    // RoPE
    {
        int total = NSEQ * NHEAD * 32 + NSEQ * KVH * 32;
        rope_kernel<<<(total + 255) / 256, 256>>>(cosT, sinT);
    }

    // Attention
    {
        int smem = (QROWS + 64 + 64) * AP * sizeof(float);  // ~68 KB
        cudaFuncSetAttribute(attn_mma,
                             cudaFuncAttributeMaxDynamicSharedMemorySize, smem);
        attn_mma<<<dim3(NHEAD, NSEQ / QROWS), 128, smem>>>(dY);
    }

    // Output projection
    gemm_tf32<<<dim3(DIM / 128, NSEQ / 128, 1), 256, gemm_smem>>>(
        dY, Wo, Wo, out, out, NSEQ, DIM, DIM);
}